// round 16
// baseline (speedup 1.0000x reference)
#include <cuda_runtime.h>
#include <cuda_bf16.h>
#include <cstdint>

#define KC 128
#define DD 128
#define TM 64
#define TPB 256
#define NCTA 456

// ---- device scratch ----
__device__ float g_acc[KC];
__device__ float g_masksum;
__device__ int   g_count;

// ---- smem layout (bytes) ----
// B persistent; staging (64 x 560) aliases A + px2 (both dead post-MMA)
#define SM_B    0                 // 32768 (C bf16, swizzled) - persistent
#define SM_A    32768             // 16384 (X bf16, swizzled)
#define SM_PX2  49152             // 8192  (x2 partials [64][32] f32)
#define SM_ST   32768             // 35840 staging (64 rows x 560 B), aliases A+px2
#define SM_X2   68608             // 256
#define SM_RIS  68864             // 256
#define SM_LMS  69120             // 256
#define SM_MS   69376             // 256
#define SM_C2   69632             // 512
#define SM_IC   70144             // 512
#define SM_SCOL 70656             // 512
#define SM_FLAG 71168             // 4
#define SM_TOTAL 71176            // x3 CTAs = 213.5 KB

#define ST_STRIDE 560             // 512 + 48 pad: conflict-free scatter + 16B aligned

__device__ __forceinline__ uint32_t smem_u32(const void* p) {
    uint32_t a;
    asm("{ .reg .u64 t; cvta.to.shared.u64 t, %1; cvt.u32.u64 %0, t; }" : "=r"(a) : "l"(p));
    return a;
}
__device__ __forceinline__ uint32_t bf2u(__nv_bfloat162 h) {
    return *reinterpret_cast<uint32_t*>(&h);
}
__device__ __forceinline__ void ldsm4(uint32_t& r0, uint32_t& r1, uint32_t& r2, uint32_t& r3,
                                      uint32_t addr) {
    asm volatile("ldmatrix.sync.aligned.m8n8.x4.shared.b16 {%0,%1,%2,%3}, [%4];"
                 : "=r"(r0), "=r"(r1), "=r"(r2), "=r"(r3) : "r"(addr));
}
__device__ __forceinline__ void mma16816(float* c, const uint32_t* a, const uint32_t* b) {
    asm volatile(
        "mma.sync.aligned.m16n8k16.row.col.f32.bf16.bf16.f32 "
        "{%0,%1,%2,%3}, {%4,%5,%6,%7}, {%8,%9}, {%0,%1,%2,%3};"
        : "+f"(c[0]), "+f"(c[1]), "+f"(c[2]), "+f"(c[3])
        : "r"(a[0]), "r"(a[1]), "r"(a[2]), "r"(a[3]), "r"(b[0]), "r"(b[1]));
}
__device__ __forceinline__ float sqrt_ap(float v) {
    float r; asm("sqrt.approx.f32 %0, %1;" : "=f"(r) : "f"(v)); return r;
}
__device__ __forceinline__ float lg2_ap(float v) {
    float r; asm("lg2.approx.f32 %0, %1;" : "=f"(r) : "f"(v)); return r;
}
__device__ __forceinline__ float rcp_ap(float v) {
    float r; asm("rcp.approx.f32 %0, %1;" : "=f"(r) : "f"(v)); return r;
}
// arg = 1 + sq*R >= 1 guaranteed (sq >= 0, R > 0) -> no clamp needed
__device__ __forceinline__ float pdist(float d, float xc, float R, float lm) {
    float sq  = fmaxf(fmaf(d, -2.0f, xc), 0.0f);
    float arg = fmaf(sq, R, 1.0f);
    float v   = arg + sqrt_ap(fmaf(arg, arg, -1.0f));
    return lg2_ap(v) * lm;
}

__global__ void __launch_bounds__(TPB, 3)
dist_kernel(const float* __restrict__ x,
            const float* __restrict__ mask,
            const float* __restrict__ cw,
            float* __restrict__ out, int N, int ntiles) {
    extern __shared__ char smem[];
    const uint32_t sb = smem_u32(smem);
    const int tid = threadIdx.x, wid = tid >> 5, l = tid & 31;
    const int wr = wid & 1, wc = wid >> 1;    // warp grid 2 (rows) x 4 (cols of 32)

    float* x2s  = (float*)(smem + SM_X2);
    float* ris  = (float*)(smem + SM_RIS);
    float* lms  = (float*)(smem + SM_LMS);
    float* ms   = (float*)(smem + SM_MS);
    float* c2s  = (float*)(smem + SM_C2);
    float* ics  = (float*)(smem + SM_IC);
    float* scol = (float*)(smem + SM_SCOL);
    float* px2  = (float*)(smem + SM_PX2);
    int*   flag = (int*)(smem + SM_FLAG);
    float* out_node = out + KC;

    // ---- inline centroid prep: 8 warps x 16 rows ----
#pragma unroll 2
    for (int r16 = 0; r16 < 16; r16++) {
        int row = wid * 16 + r16;
        float4 v = ((const float4*)(cw + (size_t)row * DD))[l];
        float ss = v.x * v.x + v.y * v.y + v.z * v.z + v.w * v.w;
#pragma unroll
        for (int o = 16; o; o >>= 1) ss += __shfl_xor_sync(0xffffffffu, ss, o);
        float norm = fmaxf(sqrtf(ss), 1e-5f);
        float s = tanhf(fminf(norm, 15.0f)) / norm;
        uint2 st;
        st.x = bf2u(__float22bfloat162_rn(make_float2(v.x * s, v.y * s)));
        st.y = bf2u(__float22bfloat162_rn(make_float2(v.z * s, v.w * s)));
        int c = l >> 1, half = l & 1;
        *(uint2*)(smem + SM_B + row * 256 + (((c ^ (row & 7)) << 4) | (half << 3))) = st;
        if (l == 0) {
            float c2 = ss * s * s;
            c2s[row] = c2;
            ics[row] = 2.0f / (1.0f - c2);
        }
    }
    if (tid < KC) scol[tid] = 0.0f;
    __syncthreads();

    const int a_row0 = wr * 32 + (l & 15);
    const int a_hi   = l >> 4;
    const int b_row0 = wc * 32 + ((l >> 4) << 3) + (l & 7);
    const int b_hi   = (l >> 3) & 1;

    float cs[8];
#pragma unroll
    for (int v = 0; v < 8; v++) cs[v] = 0.0f;
    float msacc = 0.0f;

    for (int tile = blockIdx.x; tile < ntiles; tile += NCTA) {
        const int tile0 = tile * TM;

        // ---- convert: LDG fp32 -> bf16 A tile (swizzled) + x2 partial STS ----
#pragma unroll
        for (int j = 0; j < 8; j++) {
            int i = tid + TPB * j;
            int row = i >> 5, c = i & 31;
            int gr = tile0 + row; if (gr >= N) gr = N - 1;
            float4 v = ((const float4*)x)[(size_t)gr * 32 + c];
            px2[row * 32 + c] = v.x * v.x + v.y * v.y + v.z * v.z + v.w * v.w;
            uint2 st;
            st.x = bf2u(__float22bfloat162_rn(make_float2(v.x, v.y)));
            st.y = bf2u(__float22bfloat162_rn(make_float2(v.z, v.w)));
            *(uint2*)(smem + SM_A + row * 256 +
                      ((((c >> 1) ^ (row & 7)) << 4) | ((c & 1) << 3))) = st;
        }
        if (tid < TM) {
            int gr = tile0 + tid;
            float mv = (gr < N) ? mask[gr] : 0.0f;
            ms[tid] = mv;
            msacc += mv;
        }
        __syncthreads();

        // ---- phase 2: x2 row sums + per-row epilogue constants ----
        {
            int row = tid >> 2, q = tid & 3;
            const float4* pp = (const float4*)(smem + SM_PX2 + row * 128 + q * 32);
            float4 a = pp[0], b = pp[1];
            float s = ((a.x + a.y) + (a.z + a.w)) + ((b.x + b.y) + (b.z + b.w));
            s += __shfl_xor_sync(0xffffffffu, s, 1);
            s += __shfl_xor_sync(0xffffffffu, s, 2);
            if (q == 0) {
                x2s[row] = s;
                ris[row] = rcp_ap(1.0f - s);
                lms[row] = ms[row] * 0.69314718f;
            }
        }
        __syncthreads();

        // ---- single pass: warp tile 32 rows x 32 cols, 8 k-steps ----
        float acc[2][4][4];
#pragma unroll
        for (int mi = 0; mi < 2; mi++)
#pragma unroll
            for (int t = 0; t < 4; t++)
#pragma unroll
                for (int u = 0; u < 4; u++) acc[mi][t][u] = 0.0f;

#pragma unroll
        for (int kk = 0; kk < 8; kk++) {
            uint32_t af[2][4];
#pragma unroll
            for (int mi = 0; mi < 2; mi++) {
                int row = a_row0 + mi * 16;
                uint32_t ad = sb + SM_A + row * 256
                            + ((((kk << 1) | a_hi) ^ (row & 7)) << 4);
                ldsm4(af[mi][0], af[mi][1], af[mi][2], af[mi][3], ad);
            }
            uint32_t bfr[4][2];
#pragma unroll
            for (int nt2 = 0; nt2 < 2; nt2++) {
                int nrow = b_row0 + nt2 * 16;
                uint32_t bd = sb + SM_B + nrow * 256
                            + ((((kk << 1) | b_hi) ^ (nrow & 7)) << 4);
                uint32_t r0, r1, r2, r3;
                ldsm4(r0, r1, r2, r3, bd);
                bfr[nt2 * 2][0] = r0;     bfr[nt2 * 2][1] = r1;
                bfr[nt2 * 2 + 1][0] = r2; bfr[nt2 * 2 + 1][1] = r3;
            }
#pragma unroll
            for (int mi = 0; mi < 2; mi++)
#pragma unroll
                for (int t = 0; t < 4; t++) mma16816(acc[mi][t], af[mi], bfr[t]);
        }

        __syncthreads();   // all warps done reading A/px2 -> staging may alias them

        // ---- epilogue: pdist -> staging (scattered STS, conflict-free) ----
#pragma unroll
        for (int mi = 0; mi < 2; mi++) {
#pragma unroll
            for (int rr = 0; rr < 2; rr++) {
                int r = wr * 32 + mi * 16 + rr * 8 + (l >> 2);
                float lm = lms[r], x2 = x2s[r], ri = ris[r];
#pragma unroll
                for (int t = 0; t < 4; t++) {
                    int col = wc * 32 + t * 8 + ((l & 3) << 1);
                    float2 c2p = *(float2*)(c2s + col);
                    float2 icp = *(float2*)(ics + col);
                    float d0 = pdist(acc[mi][t][rr * 2],     x2 + c2p.x, ri * icp.x, lm);
                    float d1 = pdist(acc[mi][t][rr * 2 + 1], x2 + c2p.y, ri * icp.y, lm);
                    *(float2*)(smem + SM_ST + r * ST_STRIDE + col * 4) = make_float2(d0, d1);
                    cs[t * 2]     += d0;
                    cs[t * 2 + 1] += d1;
                }
            }
        }
        __syncthreads();   // staging complete

        // ---- coalesced copy: staging -> gmem (LDS.128 + STG.128) ----
#pragma unroll
        for (int j = 0; j < 8; j++) {
            int i = tid + TPB * j;
            int row = i >> 5, c = i & 31;     // one row per warp per j
            int gr = tile0 + row;
            float4 v = *(const float4*)(smem + SM_ST + row * ST_STRIDE + c * 16);
            if (gr < N) ((float4*)(out_node + (size_t)gr * KC))[c] = v;
        }
        __syncthreads();   // staging free before next tile's convert (aliases A/px2)
    }

    // ---- one-time column-sum reduction ----
#pragma unroll
    for (int v = 0; v < 8; v++) {
        float s = cs[v];
        s += __shfl_xor_sync(0xffffffffu, s, 4);
        s += __shfl_xor_sync(0xffffffffu, s, 8);
        s += __shfl_xor_sync(0xffffffffu, s, 16);
        if (l < 4) {
            int col = wc * 32 + (v >> 1) * 8 + ((l & 3) << 1) + (v & 1);
            atomicAdd(&scol[col], s);
        }
    }
    {
        float wm = msacc;
#pragma unroll
        for (int o = 16; o; o >>= 1) wm += __shfl_xor_sync(0xffffffffu, wm, o);
        if (l == 0) atomicAdd(&g_masksum, wm);
    }
    __syncthreads();

    // ---- flush partials ----
    if (tid < KC) atomicAdd(&g_acc[tid], scol[tid]);
    __threadfence();
    __syncthreads();
    if (tid == 0) {
        int old = atomicAdd(&g_count, 1);
        *flag = (old == NCTA - 1) ? 1 : 0;
    }
    __syncthreads();
    if (*flag) {
        __threadfence();
        if (tid < KC) {
            float s  = atomicAdd(&g_acc[tid], 0.0f);
            float tm = atomicAdd(&g_masksum, 0.0f);
            out[tid] = s / tm;
        }
        __syncthreads();
        if (tid < KC) g_acc[tid] = 0.0f;
        if (tid == 0) { g_masksum = 0.0f; atomicExch(&g_count, 0); }
    }
}

extern "C" void kernel_launch(void* const* d_in, const int* in_sizes, int n_in,
                              void* d_out, int out_size) {
    const float* x    = (const float*)d_in[0];
    const float* mask = (const float*)d_in[1];
    const float* cw   = (const float*)d_in[2];
    const int N = in_sizes[1];
    float* out = (float*)d_out;

    cudaFuncSetAttribute(dist_kernel, cudaFuncAttributeMaxDynamicSharedMemorySize, SM_TOTAL);
    const int ntiles = (N + TM - 1) / TM;
    dist_kernel<<<NCTA, TPB, SM_TOTAL>>>(x, mask, cw, out, N, ntiles);
}

// round 17
// speedup vs baseline: 1.1181x; 1.1181x over previous
#include <cuda_runtime.h>
#include <cuda_bf16.h>
#include <cstdint>

#define KC 128
#define DD 128
#define TM 32        // rows per group-tile
#define TPB 256      // 2 groups x 4 warps
#define NCTA 456

// ---- device scratch ----
__device__ float g_acc[KC];
__device__ float g_masksum;
__device__ int   g_count;

// ---- smem layout (bytes); per-group arrays indexed +g*size ----
#define SM_B    0                 // 32768 (C bf16, swizzled) shared
#define SM_A    32768             // 2 x 8192  (32-row X bf16, swizzled)
#define SM_PX2  49152             // 2 x 4096  (x2 partials [32][32])
#define SM_X2   57344             // 2 x 128
#define SM_RIS  57600             // 2 x 128
#define SM_LMS  57856             // 2 x 128
#define SM_MS   58112             // 2 x 128
#define SM_C2   58368             // 512
#define SM_IC   58880             // 512
#define SM_SCOL 59392             // 512
#define SM_FLAG 59904             // 4
#define SM_TOTAL 59912            // x3 CTAs = 179.7 KB

__device__ __forceinline__ uint32_t smem_u32(const void* p) {
    uint32_t a;
    asm("{ .reg .u64 t; cvta.to.shared.u64 t, %1; cvt.u32.u64 %0, t; }" : "=r"(a) : "l"(p));
    return a;
}
__device__ __forceinline__ uint32_t bf2u(__nv_bfloat162 h) {
    return *reinterpret_cast<uint32_t*>(&h);
}
__device__ __forceinline__ void ldsm4(uint32_t& r0, uint32_t& r1, uint32_t& r2, uint32_t& r3,
                                      uint32_t addr) {
    asm volatile("ldmatrix.sync.aligned.m8n8.x4.shared.b16 {%0,%1,%2,%3}, [%4];"
                 : "=r"(r0), "=r"(r1), "=r"(r2), "=r"(r3) : "r"(addr));
}
__device__ __forceinline__ void mma16816(float* c, const uint32_t* a, const uint32_t* b) {
    asm volatile(
        "mma.sync.aligned.m16n8k16.row.col.f32.bf16.bf16.f32 "
        "{%0,%1,%2,%3}, {%4,%5,%6,%7}, {%8,%9}, {%0,%1,%2,%3};"
        : "+f"(c[0]), "+f"(c[1]), "+f"(c[2]), "+f"(c[3])
        : "r"(a[0]), "r"(a[1]), "r"(a[2]), "r"(a[3]), "r"(b[0]), "r"(b[1]));
}
__device__ __forceinline__ float sqrt_ap(float v) {
    float r; asm("sqrt.approx.f32 %0, %1;" : "=f"(r) : "f"(v)); return r;
}
__device__ __forceinline__ float lg2_ap(float v) {
    float r; asm("lg2.approx.f32 %0, %1;" : "=f"(r) : "f"(v)); return r;
}
__device__ __forceinline__ float rcp_ap(float v) {
    float r; asm("rcp.approx.f32 %0, %1;" : "=f"(r) : "f"(v)); return r;
}
// arg = 1 + sq*R >= 1 guaranteed (sq >= 0, R > 0) -> no clamp needed
__device__ __forceinline__ float pdist(float d, float xc, float R, float lm) {
    float sq  = fmaxf(fmaf(d, -2.0f, xc), 0.0f);
    float arg = fmaf(sq, R, 1.0f);
    float v   = arg + sqrt_ap(fmaf(arg, arg, -1.0f));
    return lg2_ap(v) * lm;
}
#define GBAR(gid) asm volatile("bar.sync %0, %1;" :: "r"((gid) + 1), "r"(128) : "memory")

__global__ void __launch_bounds__(TPB, 3)
dist_kernel(const float* __restrict__ x,
            const float* __restrict__ mask,
            const float* __restrict__ cw,
            float* __restrict__ out, int N, int ntiles) {
    extern __shared__ char smem[];
    const uint32_t sb = smem_u32(smem);
    const int tid = threadIdx.x, wid = tid >> 5, l = tid & 31;
    const int g = tid >> 7;                   // group 0/1
    const int ltid = tid & 127;               // thread in group
    const int wig = (tid >> 5) & 3;           // warp in group (col group of 32)

    float* c2s  = (float*)(smem + SM_C2);
    float* ics  = (float*)(smem + SM_IC);
    float* scol = (float*)(smem + SM_SCOL);
    int*   flag = (int*)(smem + SM_FLAG);
    // per-group views
    float* x2s  = (float*)(smem + SM_X2  + g * 128);
    float* ris  = (float*)(smem + SM_RIS + g * 128);
    float* lms  = (float*)(smem + SM_LMS + g * 128);
    float* ms   = (float*)(smem + SM_MS  + g * 128);
    float* px2  = (float*)(smem + SM_PX2 + g * 4096);
    const uint32_t Ag = sb + SM_A + g * 8192;
    float* out_node = out + KC;

    // ---- shared prep (whole CTA): centroids -> B tile + c2/ic ----
#pragma unroll 2
    for (int r16 = 0; r16 < 16; r16++) {
        int row = wid * 16 + r16;
        float4 v = ((const float4*)(cw + (size_t)row * DD))[l];
        float ss = v.x * v.x + v.y * v.y + v.z * v.z + v.w * v.w;
#pragma unroll
        for (int o = 16; o; o >>= 1) ss += __shfl_xor_sync(0xffffffffu, ss, o);
        float norm = fmaxf(sqrtf(ss), 1e-5f);
        float s = tanhf(fminf(norm, 15.0f)) / norm;
        uint2 st;
        st.x = bf2u(__float22bfloat162_rn(make_float2(v.x * s, v.y * s)));
        st.y = bf2u(__float22bfloat162_rn(make_float2(v.z * s, v.w * s)));
        int c = l >> 1, half = l & 1;
        *(uint2*)(smem + SM_B + row * 256 + (((c ^ (row & 7)) << 4) | (half << 3))) = st;
        if (l == 0) {
            float c2 = ss * s * s;
            c2s[row] = c2;
            ics[row] = 2.0f / (1.0f - c2);
        }
    }
    if (tid < KC) scol[tid] = 0.0f;
    __syncthreads();

    const int a_row0 = l & 15;
    const int a_hi   = l >> 4;
    const int b_row0 = wig * 32 + ((l >> 4) << 3) + (l & 7);
    const int b_hi   = (l >> 3) & 1;

    float cs[8];
#pragma unroll
    for (int v = 0; v < 8; v++) cs[v] = 0.0f;
    float msacc = 0.0f;

    // ---- per-group independent tile stream ----
    for (int tile = blockIdx.x * 2 + g; tile < ntiles; tile += NCTA * 2) {
        const int tile0 = tile * TM;

        // convert: LDG fp32 -> bf16 A (swizzled) + x2 partials
#pragma unroll
        for (int j = 0; j < 8; j++) {
            int i = ltid + 128 * j;           // 1024 chunks of 16B
            int row = i >> 5, c = i & 31;     // row warp-uniform
            int gr = tile0 + row; if (gr >= N) gr = N - 1;
            float4 v = ((const float4*)x)[(size_t)gr * 32 + c];
            px2[row * 32 + c] = v.x * v.x + v.y * v.y + v.z * v.z + v.w * v.w;
            uint2 st;
            st.x = bf2u(__float22bfloat162_rn(make_float2(v.x, v.y)));
            st.y = bf2u(__float22bfloat162_rn(make_float2(v.z, v.w)));
            *(uint2*)(smem + (Ag - sb) + row * 256 +
                      ((((c >> 1) ^ (row & 7)) << 4) | ((c & 1) << 3))) = st;
        }
        if (ltid < TM) {
            int gr = tile0 + ltid;
            float mv = (gr < N) ? mask[gr] : 0.0f;
            ms[ltid] = mv;
            msacc += mv;
        }
        GBAR(g);

        // phase 2: x2 row sums + per-row constants (4 threads/row)
        {
            int row = ltid >> 2, q = ltid & 3;
            const float4* pp = (const float4*)((const char*)px2 + row * 128 + q * 32);
            float4 a = pp[0], b = pp[1];
            float s = ((a.x + a.y) + (a.z + a.w)) + ((b.x + b.y) + (b.z + b.w));
            s += __shfl_xor_sync(0xffffffffu, s, 1);
            s += __shfl_xor_sync(0xffffffffu, s, 2);
            if (q == 0) {
                x2s[row] = s;
                ris[row] = rcp_ap(1.0f - s);
                lms[row] = ms[row] * 0.69314718f;
            }
        }
        GBAR(g);

        // mainloop: warp tile 32 rows x 32 cols, 8 k-steps
        float acc[2][4][4];
#pragma unroll
        for (int mi = 0; mi < 2; mi++)
#pragma unroll
            for (int t = 0; t < 4; t++)
#pragma unroll
                for (int u = 0; u < 4; u++) acc[mi][t][u] = 0.0f;

#pragma unroll
        for (int kk = 0; kk < 8; kk++) {
            uint32_t af[2][4];
#pragma unroll
            for (int mi = 0; mi < 2; mi++) {
                int row = a_row0 + mi * 16;
                uint32_t ad = Ag + row * 256 + ((((kk << 1) | a_hi) ^ (row & 7)) << 4);
                ldsm4(af[mi][0], af[mi][1], af[mi][2], af[mi][3], ad);
            }
            uint32_t bfr[4][2];
#pragma unroll
            for (int nt2 = 0; nt2 < 2; nt2++) {
                int nrow = b_row0 + nt2 * 16;
                uint32_t bd = sb + SM_B + nrow * 256
                            + ((((kk << 1) | b_hi) ^ (nrow & 7)) << 4);
                uint32_t r0, r1, r2, r3;
                ldsm4(r0, r1, r2, r3, bd);
                bfr[nt2 * 2][0] = r0;     bfr[nt2 * 2][1] = r1;
                bfr[nt2 * 2 + 1][0] = r2; bfr[nt2 * 2 + 1][1] = r3;
            }
#pragma unroll
            for (int mi = 0; mi < 2; mi++)
#pragma unroll
                for (int t = 0; t < 4; t++) mma16816(acc[mi][t], af[mi], bfr[t]);
        }

        // epilogue: direct scattered stores + register column sums
#pragma unroll
        for (int mi = 0; mi < 2; mi++) {
#pragma unroll
            for (int rr = 0; rr < 2; rr++) {
                int r = mi * 16 + rr * 8 + (l >> 2);
                float lm = lms[r], x2 = x2s[r], ri = ris[r];
                int gr = tile0 + r;
                float* pr = out_node + (size_t)gr * KC;
                bool ok = gr < N;
#pragma unroll
                for (int t = 0; t < 4; t++) {
                    int col = wig * 32 + t * 8 + ((l & 3) << 1);
                    float2 c2p = *(float2*)(c2s + col);
                    float2 icp = *(float2*)(ics + col);
                    float d0 = pdist(acc[mi][t][rr * 2],     x2 + c2p.x, ri * icp.x, lm);
                    float d1 = pdist(acc[mi][t][rr * 2 + 1], x2 + c2p.y, ri * icp.y, lm);
                    if (ok) *(float2*)(pr + col) = make_float2(d0, d1);
                    cs[t * 2]     += d0;
                    cs[t * 2 + 1] += d1;
                }
            }
        }
        GBAR(g);   // protect A/px2/ms/x2s before next convert
    }

    // ---- one-time column-sum reduction (both groups share col space) ----
#pragma unroll
    for (int v = 0; v < 8; v++) {
        float s = cs[v];
        s += __shfl_xor_sync(0xffffffffu, s, 4);
        s += __shfl_xor_sync(0xffffffffu, s, 8);
        s += __shfl_xor_sync(0xffffffffu, s, 16);
        if (l < 4) {
            int col = wig * 32 + (v >> 1) * 8 + ((l & 3) << 1) + (v & 1);
            atomicAdd(&scol[col], s);
        }
    }
    {
        float wm = msacc;
#pragma unroll
        for (int o = 16; o; o >>= 1) wm += __shfl_xor_sync(0xffffffffu, wm, o);
        if (l == 0) atomicAdd(&g_masksum, wm);
    }
    __syncthreads();

    // ---- flush partials ----
    if (tid < KC) atomicAdd(&g_acc[tid], scol[tid]);
    __threadfence();
    __syncthreads();
    if (tid == 0) {
        int old = atomicAdd(&g_count, 1);
        *flag = (old == NCTA - 1) ? 1 : 0;
    }
    __syncthreads();
    if (*flag) {
        __threadfence();
        if (tid < KC) {
            float s  = atomicAdd(&g_acc[tid], 0.0f);
            float tm = atomicAdd(&g_masksum, 0.0f);
            out[tid] = s / tm;
        }
        __syncthreads();
        if (tid < KC) g_acc[tid] = 0.0f;
        if (tid == 0) { g_masksum = 0.0f; atomicExch(&g_count, 0); }
    }
}

extern "C" void kernel_launch(void* const* d_in, const int* in_sizes, int n_in,
                              void* d_out, int out_size) {
    const float* x    = (const float*)d_in[0];
    const float* mask = (const float*)d_in[1];
    const float* cw   = (const float*)d_in[2];
    const int N = in_sizes[1];
    float* out = (float*)d_out;

    cudaFuncSetAttribute(dist_kernel, cudaFuncAttributeMaxDynamicSharedMemorySize, SM_TOTAL);
    const int ntiles = (N + TM - 1) / TM;
    dist_kernel<<<NCTA, TPB, SM_TOTAL>>>(x, mask, cw, out, N, ntiles);
}